// round 15
// baseline (speedup 1.0000x reference)
#include <cuda_runtime.h>
#include <cuda_bf16.h>

// Problem constants
#define B_ 4
#define S_ 2048
#define E_ 1024
#define H_ 16
#define D_ 64
#define XN (B_*S_*E_)     // 8388608
#define WN (E_*E_)        // 1048576

// ---------------- scratch ----------------
__device__ __nv_bfloat16 g_xb[XN];            // bf16 copy of x
__device__ __nv_bfloat16 g_Wb[3*WN];          // bf16 Wq|Wk|Wv
__device__ __nv_bfloat16 g_Qb[B_*H_*S_*D_];   // pre-scaled by 0.125*log2e
__device__ __nv_bfloat16 g_Kb[B_*H_*S_*D_];
__device__ __nv_bfloat16 g_Vb[B_*H_*S_*D_];
__device__ float g_pooled[B_*E_];
__device__ float g_o[B_*E_];
__device__ float g_nrm[B_];
__device__ float g_score[B_];

// ---------------- helpers ----------------
__device__ __forceinline__ void mma16(float* c, const unsigned* a, const unsigned* b) {
    asm("mma.sync.aligned.m16n8k16.row.col.f32.bf16.bf16.f32 "
        "{%0,%1,%2,%3}, {%4,%5,%6,%7}, {%8,%9}, {%0,%1,%2,%3};"
        : "+f"(c[0]), "+f"(c[1]), "+f"(c[2]), "+f"(c[3])
        : "r"(a[0]), "r"(a[1]), "r"(a[2]), "r"(a[3]), "r"(b[0]), "r"(b[1]));
}
__device__ __forceinline__ unsigned pack_bf2(float lo, float hi) {
    __nv_bfloat162 h = __floats2bfloat162_rn(lo, hi);
    return *reinterpret_cast<unsigned*>(&h);
}
__device__ __forceinline__ float ex2f(float x) {
    float r; asm("ex2.approx.f32 %0, %1;" : "=f"(r) : "f"(x)); return r;
}
__device__ __forceinline__ unsigned sptr(const void* p) {
    return (unsigned)__cvta_generic_to_shared(p);
}
__device__ __forceinline__ void ldsm4(unsigned* r, unsigned addr) {
    asm volatile("ldmatrix.sync.aligned.m8n8.x4.shared.b16 {%0,%1,%2,%3}, [%4];"
        : "=r"(r[0]), "=r"(r[1]), "=r"(r[2]), "=r"(r[3]) : "r"(addr));
}
__device__ __forceinline__ void ldsm4t(unsigned* r, unsigned addr) {
    asm volatile("ldmatrix.sync.aligned.m8n8.x4.trans.shared.b16 {%0,%1,%2,%3}, [%4];"
        : "=r"(r[0]), "=r"(r[1]), "=r"(r[2]), "=r"(r[3]) : "r"(addr));
}
__device__ __forceinline__ void cpa16(unsigned s, const void* g) {
    asm volatile("cp.async.cg.shared.global [%0], [%1], 16;" :: "r"(s), "l"(g));
}
__device__ __forceinline__ void cpcommit() { asm volatile("cp.async.commit_group;"); }
template<int N> __device__ __forceinline__ void cpwait() {
    asm volatile("cp.async.wait_group %0;" :: "n"(N));
}

#define QSCALE 0.18033688011112042f   // (1/sqrt(64)) * log2(e)

// =====================================================================
// fp32 -> bf16 conversion of x and Wq/Wk/Wv, fused with accumulator zeroing
// =====================================================================
__global__ __launch_bounds__(256) void cvt_kernel(
    const float* __restrict__ x,
    const float* __restrict__ Wq, const float* __restrict__ Wk,
    const float* __restrict__ Wv)
{
    const int i = blockIdx.x * blockDim.x + threadIdx.x;
    if (i < B_*E_) g_pooled[i] = 0.f;
    if (i < B_) { g_nrm[i] = 0.f; g_score[i] = 0.f; }
    const int total = (XN + 3*WN) / 4;
    if (i >= total) return;
    int v = i * 4;
    const float* src;
    __nv_bfloat16* dst;
    if (v < XN) {
        src = x + v; dst = g_xb + v;
    } else {
        int w = v - XN;
        int z = w / WN, r = w - z * WN;
        src = (z == 0 ? Wq : (z == 1 ? Wk : Wv)) + r;
        dst = g_Wb + z * WN + r;
    }
    float4 f = *(const float4*)src;
    *(uint2*)dst = make_uint2(pack_bf2(f.x, f.y), pack_bf2(f.z, f.w));
}

// =====================================================================
// QKV projection via bf16 mma on bf16 inputs -> bf16 scatter [B,H,S,D]
// BM=BN=128 BK=64, 256 thr (8 warps 2x4), warp tile 64x32.
// cp.async 3-stage pipeline, one sync per k-iter (16 iters).
// =====================================================================
#define QKST 72
#define QKV_STG (128 * QKST)
#define QKV_SMEM (3 * 2 * QKV_STG * 2)

__global__ __launch_bounds__(256) void qkv_mma(
    const float* __restrict__ bq, const float* __restrict__ bk,
    const float* __restrict__ bv)
{
    extern __shared__ __align__(16) char qsm[];
    __nv_bfloat16* As = (__nv_bfloat16*)qsm;
    __nv_bfloat16* Bs = As + 3 * QKV_STG;

    const int z = blockIdx.z;
    const float* __restrict__ bias = (z == 0) ? bq : ((z == 1) ? bk : bv);
    __nv_bfloat16* __restrict__ out = (z == 0) ? g_Qb : ((z == 1) ? g_Kb : g_Vb);
    const float qsc = (z == 0) ? QSCALE : 1.f;

    const int tid  = threadIdx.x;
    const int lane = tid & 31, wid = tid >> 5;
    const int wm = wid >> 2, wn = wid & 3;
    const int m0 = blockIdx.y * 128, n0 = blockIdx.x * 128;
    const int g = lane >> 2, t = lane & 3;

    const __nv_bfloat16* Xg = g_xb + (size_t)m0 * E_;
    const __nv_bfloat16* Wg = g_Wb + (size_t)z * WN + (size_t)n0 * E_;

    const int crow = tid >> 3;
    const int ccol = (tid & 7) * 8;

    const unsigned aS0 = sptr(As) + (unsigned)(crow * QKST + ccol) * 2;
    const unsigned bS0 = sptr(Bs) + (unsigned)(crow * QKST + ccol) * 2;

    auto issue = [&](int kt, int s) {
        unsigned so = (unsigned)(s * QKV_STG * 2);
        const __nv_bfloat16* xa = Xg + (size_t)crow * E_ + kt * 64 + ccol;
        const __nv_bfloat16* wb = Wg + (size_t)crow * E_ + kt * 64 + ccol;
        #pragma unroll
        for (int it = 0; it < 4; it++) {
            cpa16(aS0 + so + it * (32 * QKST * 2), xa + (size_t)(it * 32) * E_);
            cpa16(bS0 + so + it * (32 * QKST * 2), wb + (size_t)(it * 32) * E_);
        }
        cpcommit();
    };

    const unsigned aBase = sptr(As) +
        (unsigned)((wm*64 + (lane & 15)) * QKST + (lane >> 4) * 8) * 2;
    const unsigned bBase = sptr(Bs) +
        (unsigned)((wn*32 + (lane & 7) + ((lane & 16) >> 1)) * QKST + ((lane >> 3) & 1) * 8) * 2;

    float acc[4][4][4];
    #pragma unroll
    for (int mt = 0; mt < 4; mt++)
        #pragma unroll
        for (int nt = 0; nt < 4; nt++)
            #pragma unroll
            for (int j = 0; j < 4; j++) acc[mt][nt][j] = 0.f;

    issue(0, 0);
    issue(1, 1);

    for (int i = 0; i < 16; i++) {
        if (i < 15) cpwait<1>(); else cpwait<0>();
        __syncthreads();
        if (i + 2 < 16) issue(i + 2, (i + 2) % 3);

        const unsigned so = (unsigned)((i % 3) * QKV_STG * 2);
        #pragma unroll
        for (int ks = 0; ks < 4; ks++) {
            unsigned a[4][4];
            #pragma unroll
            for (int mt = 0; mt < 4; mt++)
                ldsm4(a[mt], aBase + so + mt * (16 * QKST * 2) + ks * 32);
            #pragma unroll
            for (int p = 0; p < 2; p++) {
                unsigned bb[4];
                ldsm4(bb, bBase + so + p * (16 * QKST * 2) + ks * 32);
                #pragma unroll
                for (int mt = 0; mt < 4; mt++) {
                    mma16(acc[mt][2*p    ], a[mt], bb);
                    mma16(acc[mt][2*p + 1], a[mt], bb + 2);
                }
            }
        }
    }

    #pragma unroll
    for (int nt = 0; nt < 4; nt++) {
        int coln = n0 + wn * 32 + nt * 8 + 2 * t;
        int h = coln >> 6, d = coln & 63;
        float bv0 = bias[coln], bv1 = bias[coln + 1];
        #pragma unroll
        for (int mt = 0; mt < 4; mt++) {
            int gm = m0 + wm * 64 + mt * 16 + g;
            int bb = gm >> 11, s = gm & (S_ - 1);
            __nv_bfloat16* op = out + (size_t)((bb*H_ + h)*S_ + s) * D_ + d;
            *(unsigned*)op = pack_bf2((acc[mt][nt][0] + bv0) * qsc,
                                      (acc[mt][nt][1] + bv1) * qsc);
            *(unsigned*)(op + 8*D_) = pack_bf2((acc[mt][nt][2] + bv0) * qsc,
                                               (acc[mt][nt][3] + bv1) * qsc);
        }
    }
}

// =====================================================================
// Flash attention: bf16 mma + ldmatrix + ex2 softmax (log2 domain).
// 128-thread blocks (4 warps x 32 rows, mt=2), 2 blocks/SM so one
// block's softmax overlaps the other's MMA phase. K/V via cp.async
// 3-stage; Q and P fragments live in registers.
// =====================================================================
#define AST 72
#define QROWS 128
#define Q_BYTES   (QROWS * AST * 2)
#define KV_BYTES  (64 * AST * 2)            // one K or V tile
#define ATTN_SMEM (Q_BYTES + 3 * 2 * KV_BYTES + 2 * 64 * 4 + 64 * 4)

__global__ __launch_bounds__(128, 2) void attn_mma(const int* __restrict__ mask)
{
    extern __shared__ __align__(16) char smraw[];
    __nv_bfloat16* Qs = (__nv_bfloat16*)smraw;          // [128][AST]
    __nv_bfloat16* Ks = Qs + QROWS * AST;               // stage s: K at s*2*KV, V at +KV
    float* smf   = (float*)(smraw + Q_BYTES + 3 * 2 * KV_BYTES);  // [2][64]
    float* spool = smf + 128;                                     // [64]

    const int tid  = threadIdx.x;
    const int lane = tid & 31, wid = tid >> 5;
    const int t = lane & 3;
    const int wrow = wid * 32;
    const int bh = blockIdx.y, b = bh >> 4;
    const int m0 = blockIdx.x * QROWS;

    const __nv_bfloat16* Qg = g_Qb + (size_t)(bh * S_ + m0) * D_;
    const __nv_bfloat16* Kg = g_Kb + (size_t)bh * S_ * D_;
    const __nv_bfloat16* Vg = g_Vb + (size_t)bh * S_ * D_;

    const unsigned qA = sptr(&Qs[(wrow + (lane & 15)) * AST + (lane >> 4) * 8]);
    const unsigned kB = sptr(&Ks[((lane & 7) + ((lane & 16) >> 1)) * AST + ((lane >> 3) & 1) * 8]);
    const unsigned vBr = sptr(&Ks[(lane & 15) * AST + (lane >> 4) * 8]) + (unsigned)KV_BYTES;

    // Q tile copy (already pre-scaled bf16)
    #pragma unroll
    for (int it = 0; it < 8; it++) {
        int lin = tid + it * 128;                 // 0..1023
        int rr = lin >> 3, c8 = (lin & 7) * 8;
        *(uint4*)&Qs[rr * AST + c8] = *(const uint4*)(Qg + (size_t)rr * D_ + c8);
    }
    if (tid < 64) spool[tid] = 0.f;

    // K/V cp.async stage loader: tile kt -> slot s.
    // Each thread covers one 32-column half-row (64 bytes) of K and of V:
    // 4 x 16B chunks each.
    const int krow = tid >> 1;                    // 0..63
    const int kcol = (tid & 1) * 32;              // 0 or 32
    auto issue_kv = [&](int kt, int s) {
        const unsigned so = sptr(Ks) + (unsigned)(s * 2 * KV_BYTES);
        const __nv_bfloat16* kp = Kg + (size_t)(kt * 64 + krow) * D_ + kcol;
        const __nv_bfloat16* vp = Vg + (size_t)(kt * 64 + krow) * D_ + kcol;
        const unsigned dst = so + (unsigned)(krow * AST + kcol) * 2;
        #pragma unroll
        for (int c = 0; c < 4; c++) {
            cpa16(dst + c * 16,                        kp + c * 8);
            cpa16(dst + (unsigned)KV_BYTES + c * 16,   vp + c * 8);
        }
        cpcommit();
    };

    float oac[2][8][4];
    #pragma unroll
    for (int mt = 0; mt < 2; mt++)
        #pragma unroll
        for (int dt = 0; dt < 8; dt++)
            #pragma unroll
            for (int j = 0; j < 4; j++) oac[mt][dt][j] = 0.f;
    float lsum[2][2] = {{0.f, 0.f}, {0.f, 0.f}};

    // prologue: stage 0,1 in flight; mask tile0 -> smf[0], tile1 staged in pm
    int pm = 1;
    issue_kv(0, 0);
    issue_kv(1, 1);
    if (tid < 64) smf[tid] = mask[b * S_ + tid] ? 0.f : -1e9f;
    if (tid < 64) pm = mask[b * S_ + 64 + tid];
    __syncthreads();

    // hoist Q fragments: qa[ks][mt][4]
    unsigned qa[4][2][4];
    #pragma unroll
    for (int ks = 0; ks < 4; ks++)
        #pragma unroll
        for (int mt = 0; mt < 2; mt++)
            ldsm4(qa[ks][mt], qA + mt * (16 * AST * 2) + ks * 32);

    for (int i = 0; i < 32; i++) {
        if (i < 31) cpwait<1>(); else cpwait<0>();
        __syncthreads();
        if (i + 2 < 32) issue_kv(i + 2, (i + 2) % 3);
        // mask double-buffer: write tile i+1 into smf[(i+1)&1], prefetch tile i+2
        if (i + 1 < 32 && tid < 64) smf[((i + 1) & 1) * 64 + tid] = pm ? 0.f : -1e9f;
        if (i + 2 < 32 && tid < 64) pm = mask[b * S_ + (i + 2) * 64 + tid];

        const unsigned cb = (unsigned)((i % 3) * 2 * KV_BYTES);

        // ---- QK + exp in two nt-halves ----
        unsigned pfrag[2][16];
        const float* mfb = smf + (i & 1) * 64;
        #pragma unroll
        for (int h = 0; h < 2; h++) {
            float sc[2][4][4];
            #pragma unroll
            for (int mt = 0; mt < 2; mt++)
                #pragma unroll
                for (int l = 0; l < 4; l++)
                    #pragma unroll
                    for (int j = 0; j < 4; j++) sc[mt][l][j] = 0.f;

            #pragma unroll
            for (int ks = 0; ks < 4; ks++) {
                #pragma unroll
                for (int pp = 0; pp < 2; pp++) {
                    int p = 2*h + pp;
                    unsigned bb[4];
                    ldsm4(bb, kB + cb + p * (16 * AST * 2) + ks * 32);
                    #pragma unroll
                    for (int mt = 0; mt < 2; mt++) {
                        mma16(sc[mt][2*pp    ], qa[ks][mt], bb);
                        mma16(sc[mt][2*pp + 1], qa[ks][mt], bb + 2);
                    }
                }
            }
            #pragma unroll
            for (int l = 0; l < 4; l++) {
                int gnt = 4*h + l;
                float2 mf = *(const float2*)&mfb[gnt*8 + 2*t];
                #pragma unroll
                for (int mt = 0; mt < 2; mt++) {
                    float e0 = ex2f(sc[mt][l][0] + mf.x);
                    float e1 = ex2f(sc[mt][l][1] + mf.y);
                    float e2 = ex2f(sc[mt][l][2] + mf.x);
                    float e3 = ex2f(sc[mt][l][3] + mf.y);
                    lsum[mt][0] += e0 + e1;
                    lsum[mt][1] += e2 + e3;
                    pfrag[mt][2*gnt    ] = pack_bf2(e0, e1);
                    pfrag[mt][2*gnt + 1] = pack_bf2(e2, e3);
                }
            }
        }

        // ---- O += P V (V B-fragments via ldmatrix.trans) ----
        #pragma unroll
        for (int ks = 0; ks < 4; ks++) {
            #pragma unroll
            for (int p = 0; p < 4; p++) {
                unsigned bb[4];
                ldsm4t(bb, vBr + cb + ks * (16 * AST * 2) + p * 32);
                #pragma unroll
                for (int mt = 0; mt < 2; mt++) {
                    mma16(oac[mt][2*p    ], &pfrag[mt][4*ks], bb);
                    mma16(oac[mt][2*p + 1], &pfrag[mt][4*ks], bb + 2);
                }
            }
        }
    }

    // ---- epilogue: normalize rows, block-local pooled reduction ----
    #pragma unroll
    for (int mt = 0; mt < 2; mt++)
        #pragma unroll
        for (int j = 0; j < 2; j++) {
            float v = lsum[mt][j];
            v += __shfl_xor_sync(0xffffffffu, v, 1);
            v += __shfl_xor_sync(0xffffffffu, v, 2);
            lsum[mt][j] = 1.f / v;
        }

    #pragma unroll
    for (int dt = 0; dt < 8; dt++) {
        float p0 = oac[0][dt][0]*lsum[0][0] + oac[0][dt][2]*lsum[0][1]
                 + oac[1][dt][0]*lsum[1][0] + oac[1][dt][2]*lsum[1][1];
        float p1 = oac[0][dt][1]*lsum[0][0] + oac[0][dt][3]*lsum[0][1]
                 + oac[1][dt][1]*lsum[1][0] + oac[1][dt][3]*lsum[1][1];
        p0 += __shfl_xor_sync(0xffffffffu, p0, 4);
        p0 += __shfl_xor_sync(0xffffffffu, p0, 8);
        p0 += __shfl_xor_sync(0xffffffffu, p0, 16);
        p1 += __shfl_xor_sync(0xffffffffu, p1, 4);
        p1 += __shfl_xor_sync(0xffffffffu, p1, 8);
        p1 += __shfl_xor_sync(0xffffffffu, p1, 16);
        if (lane < 4) {
            atomicAdd(&spool[dt*8 + 2*t    ], p0);
            atomicAdd(&spool[dt*8 + 2*t + 1], p1);
        }
    }
    __syncthreads();
    if (tid < 64) {
        const int h = bh & 15;
        atomicAdd(&g_pooled[b*E_ + h*64 + tid], spool[tid]);
    }
}

// =====================================================================
// head A: o = (pooled/S) @ Wo^T + bo ; accumulate squared norm
// =====================================================================
__global__ __launch_bounds__(256) void headA_kernel(
    const float* __restrict__ Wo, const float* __restrict__ bo)
{
    const int b = blockIdx.y;
    const int n = blockIdx.x * 8 + (threadIdx.x >> 5);
    const int lane = threadIdx.x & 31;
    const float* pr = g_pooled + b * E_;
    const float* wr = Wo + (size_t)n * E_;
    float acc = 0.f;
    #pragma unroll
    for (int i = 0; i < 8; i++) {
        int k = i * 128 + lane * 4;
        float4 w = *(const float4*)(wr + k);
        float4 p = *(const float4*)(pr + k);
        acc += p.x*w.x + p.y*w.y + p.z*w.z + p.w*w.w;
    }
    #pragma unroll
    for (int off = 16; off > 0; off >>= 1)
        acc += __shfl_xor_sync(0xffffffffu, acc, off);
    if (lane == 0) {
        float o = acc * (1.0f / S_) + bo[n];
        g_o[b * E_ + n] = o;
        atomicAdd(&g_nrm[b], o * o);
    }
}

// =====================================================================
// head B: u = o/||o|| - text ; h = relu(u @ W1^T + b1) ; score += h*W2
// =====================================================================
__global__ __launch_bounds__(256) void headB_kernel(
    const float* __restrict__ text,
    const float* __restrict__ W1, const float* __restrict__ b1,
    const float* __restrict__ W2)
{
    const int b = blockIdx.y;
    const int rr = blockIdx.x * 8 + (threadIdx.x >> 5);
    const int lane = threadIdx.x & 31;
    const float rinv = rsqrtf(g_nrm[b]);
    const float* orow = g_o + b * E_;
    const float* trow = text + b * E_;
    const float* wr = W1 + (size_t)rr * E_;
    float acc = 0.f;
    #pragma unroll
    for (int i = 0; i < 8; i++) {
        int k = i * 128 + lane * 4;
        float4 w = *(const float4*)(wr + k);
        float4 o = *(const float4*)(orow + k);
        float4 tt = *(const float4*)(trow + k);
        acc += (o.x*rinv - tt.x)*w.x + (o.y*rinv - tt.y)*w.y
             + (o.z*rinv - tt.z)*w.z + (o.w*rinv - tt.w)*w.w;
    }
    #pragma unroll
    for (int off = 16; off > 0; off >>= 1)
        acc += __shfl_xor_sync(0xffffffffu, acc, off);
    if (lane == 0) {
        float hv = fmaxf(acc + b1[rr], 0.f);
        atomicAdd(&g_score[b], hv * W2[rr]);
    }
}

__global__ void headC_kernel(const float* __restrict__ b2, float* __restrict__ out)
{
    int i = threadIdx.x;
    if (i < B_) out[i] = tanhf(g_score[i] + b2[0]);
}

// =====================================================================
// Launch
// =====================================================================
extern "C" void kernel_launch(void* const* d_in, const int* in_sizes, int n_in,
                              void* d_out, int out_size)
{
    (void)in_sizes; (void)n_in; (void)out_size;
    const float* x    = (const float*)d_in[0];
    const int*   mask = (const int*)  d_in[1];
    const float* text = (const float*)d_in[2];
    const float* Wq = (const float*)d_in[3];
    const float* bq = (const float*)d_in[4];
    const float* Wk = (const float*)d_in[5];
    const float* bk = (const float*)d_in[6];
    const float* Wv = (const float*)d_in[7];
    const float* bv = (const float*)d_in[8];
    const float* Wo = (const float*)d_in[9];
    const float* bo = (const float*)d_in[10];
    const float* W1 = (const float*)d_in[11];
    const float* b1 = (const float*)d_in[12];
    const float* W2 = (const float*)d_in[13];
    const float* b2 = (const float*)d_in[14];
    float* out = (float*)d_out;

    cudaFuncSetAttribute(attn_mma, cudaFuncAttributeMaxDynamicSharedMemorySize, ATTN_SMEM);
    cudaFuncSetAttribute(qkv_mma, cudaFuncAttributeMaxDynamicSharedMemorySize, QKV_SMEM);

    {
        int total = (XN + 3*WN) / 4;
        cvt_kernel<<<(total + 255) / 256, 256>>>(x, Wq, Wk, Wv);
    }
    qkv_mma<<<dim3(8, 64, 3), 256, QKV_SMEM>>>(bq, bk, bv);
    attn_mma<<<dim3(16, 64), 128, ATTN_SMEM>>>(mask);
    headA_kernel<<<dim3(128, B_), 256>>>(Wo, bo);
    headB_kernel<<<dim3(64, B_), 256>>>(text, W1, b1, W2);
    headC_kernel<<<1, 32>>>(b2, out);
}

// round 16
// speedup vs baseline: 1.7092x; 1.7092x over previous
#include <cuda_runtime.h>
#include <cuda_bf16.h>

// Problem constants
#define B_ 4
#define S_ 2048
#define E_ 1024
#define H_ 16
#define D_ 64
#define XN (B_*S_*E_)     // 8388608
#define WN (E_*E_)        // 1048576

// ---------------- scratch ----------------
__device__ __nv_bfloat16 g_xb[XN];            // bf16 copy of x
__device__ __nv_bfloat16 g_Wb[3*WN];          // bf16 Wq|Wk|Wv
__device__ __nv_bfloat16 g_Qb[B_*H_*S_*D_];   // pre-scaled by 0.125*log2e
__device__ __nv_bfloat16 g_Kb[B_*H_*S_*D_];
__device__ __nv_bfloat16 g_Vb[B_*H_*S_*D_];
__device__ float g_pooled[B_*E_];
__device__ float g_o[B_*E_];
__device__ float g_nrm[B_];
__device__ float g_score[B_];

// ---------------- helpers ----------------
__device__ __forceinline__ void mma16(float* c, const unsigned* a, const unsigned* b) {
    asm("mma.sync.aligned.m16n8k16.row.col.f32.bf16.bf16.f32 "
        "{%0,%1,%2,%3}, {%4,%5,%6,%7}, {%8,%9}, {%0,%1,%2,%3};"
        : "+f"(c[0]), "+f"(c[1]), "+f"(c[2]), "+f"(c[3])
        : "r"(a[0]), "r"(a[1]), "r"(a[2]), "r"(a[3]), "r"(b[0]), "r"(b[1]));
}
__device__ __forceinline__ unsigned pack_bf2(float lo, float hi) {
    __nv_bfloat162 h = __floats2bfloat162_rn(lo, hi);
    return *reinterpret_cast<unsigned*>(&h);
}
__device__ __forceinline__ float ex2f(float x) {
    float r; asm("ex2.approx.f32 %0, %1;" : "=f"(r) : "f"(x)); return r;
}
__device__ __forceinline__ unsigned sptr(const void* p) {
    return (unsigned)__cvta_generic_to_shared(p);
}
__device__ __forceinline__ void ldsm4(unsigned* r, unsigned addr) {
    asm volatile("ldmatrix.sync.aligned.m8n8.x4.shared.b16 {%0,%1,%2,%3}, [%4];"
        : "=r"(r[0]), "=r"(r[1]), "=r"(r[2]), "=r"(r[3]) : "r"(addr));
}
__device__ __forceinline__ void ldsm4t(unsigned* r, unsigned addr) {
    asm volatile("ldmatrix.sync.aligned.m8n8.x4.trans.shared.b16 {%0,%1,%2,%3}, [%4];"
        : "=r"(r[0]), "=r"(r[1]), "=r"(r[2]), "=r"(r[3]) : "r"(addr));
}
__device__ __forceinline__ void cpa16(unsigned s, const void* g) {
    asm volatile("cp.async.cg.shared.global [%0], [%1], 16;" :: "r"(s), "l"(g));
}
__device__ __forceinline__ void cpcommit() { asm volatile("cp.async.commit_group;"); }
template<int N> __device__ __forceinline__ void cpwait() {
    asm volatile("cp.async.wait_group %0;" :: "n"(N));
}

#define QSCALE 0.18033688011112042f   // (1/sqrt(64)) * log2(e)

// =====================================================================
// fp32 -> bf16 conversion of x and Wq/Wk/Wv, fused with accumulator zeroing
// =====================================================================
__global__ __launch_bounds__(256) void cvt_kernel(
    const float* __restrict__ x,
    const float* __restrict__ Wq, const float* __restrict__ Wk,
    const float* __restrict__ Wv)
{
    const int i = blockIdx.x * blockDim.x + threadIdx.x;
    if (i < B_*E_) g_pooled[i] = 0.f;
    if (i < B_) { g_nrm[i] = 0.f; g_score[i] = 0.f; }
    const int total = (XN + 3*WN) / 4;
    if (i >= total) return;
    int v = i * 4;
    const float* src;
    __nv_bfloat16* dst;
    if (v < XN) {
        src = x + v; dst = g_xb + v;
    } else {
        int w = v - XN;
        int z = w / WN, r = w - z * WN;
        src = (z == 0 ? Wq : (z == 1 ? Wk : Wv)) + r;
        dst = g_Wb + z * WN + r;
    }
    float4 f = *(const float4*)src;
    *(uint2*)dst = make_uint2(pack_bf2(f.x, f.y), pack_bf2(f.z, f.w));
}

// =====================================================================
// QKV projection via bf16 mma on bf16 inputs -> bf16 scatter [B,H,S,D]
// BM=BN=128 BK=64, 256 thr (8 warps 2x4), warp tile 64x32.
// cp.async 3-stage pipeline, one sync per k-iter (16 iters).
// 2 blocks/SM (221KB smem, regs capped by launch bounds).
// =====================================================================
#define QKST 72
#define QKV_STG (128 * QKST)
#define QKV_SMEM (3 * 2 * QKV_STG * 2)

__global__ __launch_bounds__(256, 2) void qkv_mma(
    const float* __restrict__ bq, const float* __restrict__ bk,
    const float* __restrict__ bv)
{
    extern __shared__ __align__(16) char qsm[];
    __nv_bfloat16* As = (__nv_bfloat16*)qsm;
    __nv_bfloat16* Bs = As + 3 * QKV_STG;

    const int z = blockIdx.z;
    const float* __restrict__ bias = (z == 0) ? bq : ((z == 1) ? bk : bv);
    __nv_bfloat16* __restrict__ out = (z == 0) ? g_Qb : ((z == 1) ? g_Kb : g_Vb);
    const float qsc = (z == 0) ? QSCALE : 1.f;

    const int tid  = threadIdx.x;
    const int lane = tid & 31, wid = tid >> 5;
    const int wm = wid >> 2, wn = wid & 3;
    const int m0 = blockIdx.y * 128, n0 = blockIdx.x * 128;
    const int g = lane >> 2, t = lane & 3;

    const __nv_bfloat16* Xg = g_xb + (size_t)m0 * E_;
    const __nv_bfloat16* Wg = g_Wb + (size_t)z * WN + (size_t)n0 * E_;

    const int crow = tid >> 3;
    const int ccol = (tid & 7) * 8;

    const unsigned aS0 = sptr(As) + (unsigned)(crow * QKST + ccol) * 2;
    const unsigned bS0 = sptr(Bs) + (unsigned)(crow * QKST + ccol) * 2;

    auto issue = [&](int kt, int s) {
        unsigned so = (unsigned)(s * QKV_STG * 2);
        const __nv_bfloat16* xa = Xg + (size_t)crow * E_ + kt * 64 + ccol;
        const __nv_bfloat16* wb = Wg + (size_t)crow * E_ + kt * 64 + ccol;
        #pragma unroll
        for (int it = 0; it < 4; it++) {
            cpa16(aS0 + so + it * (32 * QKST * 2), xa + (size_t)(it * 32) * E_);
            cpa16(bS0 + so + it * (32 * QKST * 2), wb + (size_t)(it * 32) * E_);
        }
        cpcommit();
    };

    const unsigned aBase = sptr(As) +
        (unsigned)((wm*64 + (lane & 15)) * QKST + (lane >> 4) * 8) * 2;
    const unsigned bBase = sptr(Bs) +
        (unsigned)((wn*32 + (lane & 7) + ((lane & 16) >> 1)) * QKST + ((lane >> 3) & 1) * 8) * 2;

    float acc[4][4][4];
    #pragma unroll
    for (int mt = 0; mt < 4; mt++)
        #pragma unroll
        for (int nt = 0; nt < 4; nt++)
            #pragma unroll
            for (int j = 0; j < 4; j++) acc[mt][nt][j] = 0.f;

    issue(0, 0);
    issue(1, 1);

    for (int i = 0; i < 16; i++) {
        if (i < 15) cpwait<1>(); else cpwait<0>();
        __syncthreads();
        if (i + 2 < 16) issue(i + 2, (i + 2) % 3);

        const unsigned so = (unsigned)((i % 3) * QKV_STG * 2);
        #pragma unroll
        for (int ks = 0; ks < 4; ks++) {
            unsigned a[4][4];
            #pragma unroll
            for (int mt = 0; mt < 4; mt++)
                ldsm4(a[mt], aBase + so + mt * (16 * QKST * 2) + ks * 32);
            #pragma unroll
            for (int p = 0; p < 2; p++) {
                unsigned bb[4];
                ldsm4(bb, bBase + so + p * (16 * QKST * 2) + ks * 32);
                #pragma unroll
                for (int mt = 0; mt < 4; mt++) {
                    mma16(acc[mt][2*p    ], a[mt], bb);
                    mma16(acc[mt][2*p + 1], a[mt], bb + 2);
                }
            }
        }
    }

    #pragma unroll
    for (int nt = 0; nt < 4; nt++) {
        int coln = n0 + wn * 32 + nt * 8 + 2 * t;
        int h = coln >> 6, d = coln & 63;
        float bv0 = bias[coln], bv1 = bias[coln + 1];
        #pragma unroll
        for (int mt = 0; mt < 4; mt++) {
            int gm = m0 + wm * 64 + mt * 16 + g;
            int bb = gm >> 11, s = gm & (S_ - 1);
            __nv_bfloat16* op = out + (size_t)((bb*H_ + h)*S_ + s) * D_ + d;
            *(unsigned*)op = pack_bf2((acc[mt][nt][0] + bv0) * qsc,
                                      (acc[mt][nt][1] + bv1) * qsc);
            *(unsigned*)(op + 8*D_) = pack_bf2((acc[mt][nt][2] + bv0) * qsc,
                                               (acc[mt][nt][3] + bv1) * qsc);
        }
    }
}

// =====================================================================
// Flash attention: bf16 mma + ldmatrix + ex2 softmax (log2 domain).
// 256 q rows/block: 8 warps x 32 rows (mt=2). Key tile 64, double-buffered
// K/V, Q and P fragments in registers, QK split in two nt-halves.
// (R12 configuration — best measured.)
// =====================================================================
#define AST 72
#define QROWS 256
#define Q_BYTES   (QROWS * AST * 2)
#define KV_BYTES  (64 * AST * 2)
#define ATTN_SMEM (Q_BYTES + 4 * KV_BYTES + 2 * 64 * 4 + 64 * 4)

__global__ __launch_bounds__(256, 1) void attn_mma(const int* __restrict__ mask)
{
    extern __shared__ __align__(16) char smraw[];
    __nv_bfloat16* Qs = (__nv_bfloat16*)smraw;          // [256][AST]
    __nv_bfloat16* Ks = Qs + QROWS * AST;               // buf0: K,V ; buf1: K,V
    __nv_bfloat16* Vs = Ks + 64 * AST;
    float* smf   = (float*)(smraw + Q_BYTES + 4 * KV_BYTES);  // [2][64]
    float* spool = smf + 128;                                 // [64]

    const int tid  = threadIdx.x;
    const int lane = tid & 31, wid = tid >> 5;
    const int t = lane & 3;
    const int wrow = wid * 32;
    const int bh = blockIdx.y, b = bh >> 4;
    const int m0 = blockIdx.x * QROWS;
    const unsigned KVB = 2 * KV_BYTES;

    const __nv_bfloat16* Qg = g_Qb + (size_t)(bh * S_ + m0) * D_;
    const __nv_bfloat16* Kg = g_Kb + (size_t)bh * S_ * D_;
    const __nv_bfloat16* Vg = g_Vb + (size_t)bh * S_ * D_;

    const unsigned qA = sptr(&Qs[(wrow + (lane & 15)) * AST + (lane >> 4) * 8]);
    const unsigned kB = sptr(&Ks[((lane & 7) + ((lane & 16) >> 1)) * AST + ((lane >> 3) & 1) * 8]);
    const unsigned vB = sptr(&Vs[(lane & 15) * AST + (lane >> 4) * 8]);

    #pragma unroll
    for (int it = 0; it < 8; it++) {
        int lin = tid + it * 256;
        int rr = lin >> 3, c8 = (lin & 7) * 8;
        *(uint4*)&Qs[rr * AST + c8] = *(const uint4*)(Qg + (size_t)rr * D_ + c8);
    }
    if (tid < 64) spool[tid] = 0.f;

    float oac[2][8][4];
    #pragma unroll
    for (int mt = 0; mt < 2; mt++)
        #pragma unroll
        for (int dt = 0; dt < 8; dt++)
            #pragma unroll
            for (int j = 0; j < 4; j++) oac[mt][dt][j] = 0.f;
    float lsum[2][2] = {{0.f, 0.f}, {0.f, 0.f}};

    const int rr0 = tid >> 3, c8_ = (tid & 7) * 8;
    const int rr1 = rr0 + 32;

    uint4 pk[2], pv[2]; int pm = 1;
    pk[0] = *(const uint4*)(Kg + (size_t)rr0 * D_ + c8_);
    pk[1] = *(const uint4*)(Kg + (size_t)rr1 * D_ + c8_);
    pv[0] = *(const uint4*)(Vg + (size_t)rr0 * D_ + c8_);
    pv[1] = *(const uint4*)(Vg + (size_t)rr1 * D_ + c8_);
    *(uint4*)&Ks[rr0 * AST + c8_] = pk[0];
    *(uint4*)&Ks[rr1 * AST + c8_] = pk[1];
    *(uint4*)&Vs[rr0 * AST + c8_] = pv[0];
    *(uint4*)&Vs[rr1 * AST + c8_] = pv[1];
    if (tid < 64) smf[tid] = mask[b * S_ + tid] ? 0.f : -1e9f;
    pk[0] = *(const uint4*)(Kg + (size_t)(64 + rr0) * D_ + c8_);
    pk[1] = *(const uint4*)(Kg + (size_t)(64 + rr1) * D_ + c8_);
    pv[0] = *(const uint4*)(Vg + (size_t)(64 + rr0) * D_ + c8_);
    pv[1] = *(const uint4*)(Vg + (size_t)(64 + rr1) * D_ + c8_);
    if (tid < 64) pm = mask[b * S_ + 64 + tid];
    __syncthreads();

    unsigned qa[4][2][4];
    #pragma unroll
    for (int ks = 0; ks < 4; ks++)
        #pragma unroll
        for (int mt = 0; mt < 2; mt++)
            ldsm4(qa[ks][mt], qA + mt * (16 * AST * 2) + ks * 32);

    for (int i = 0; i < 32; i++) {
        const unsigned cb = (i & 1) * KVB;
        const int nxt = (i + 1) & 1;
        if (i + 1 < 32) {
            __nv_bfloat16* Kn = Ks + nxt * (KVB / 2);
            __nv_bfloat16* Vn = Vs + nxt * (KVB / 2);
            *(uint4*)&Kn[rr0 * AST + c8_] = pk[0];
            *(uint4*)&Kn[rr1 * AST + c8_] = pk[1];
            *(uint4*)&Vn[rr0 * AST + c8_] = pv[0];
            *(uint4*)&Vn[rr1 * AST + c8_] = pv[1];
            if (tid < 64) smf[nxt * 64 + tid] = pm ? 0.f : -1e9f;
        }
        if (i + 2 < 32) {
            size_t base = (size_t)((i + 2) * 64);
            pk[0] = *(const uint4*)(Kg + (base + rr0) * D_ + c8_);
            pk[1] = *(const uint4*)(Kg + (base + rr1) * D_ + c8_);
            pv[0] = *(const uint4*)(Vg + (base + rr0) * D_ + c8_);
            pv[1] = *(const uint4*)(Vg + (base + rr1) * D_ + c8_);
            if (tid < 64) pm = mask[b * S_ + (i + 2) * 64 + tid];
        }

        unsigned pfrag[2][16];
        const float* mfb = smf + (i & 1) * 64;
        #pragma unroll
        for (int h = 0; h < 2; h++) {
            float sc[2][4][4];
            #pragma unroll
            for (int mt = 0; mt < 2; mt++)
                #pragma unroll
                for (int l = 0; l < 4; l++)
                    #pragma unroll
                    for (int j = 0; j < 4; j++) sc[mt][l][j] = 0.f;

            #pragma unroll
            for (int ks = 0; ks < 4; ks++) {
                #pragma unroll
                for (int pp = 0; pp < 2; pp++) {
                    int p = 2*h + pp;
                    unsigned bb[4];
                    ldsm4(bb, kB + cb + p * (16 * AST * 2) + ks * 32);
                    #pragma unroll
                    for (int mt = 0; mt < 2; mt++) {
                        mma16(sc[mt][2*pp    ], qa[ks][mt], bb);
                        mma16(sc[mt][2*pp + 1], qa[ks][mt], bb + 2);
                    }
                }
            }
            #pragma unroll
            for (int l = 0; l < 4; l++) {
                int gnt = 4*h + l;
                float2 mf = *(const float2*)&mfb[gnt*8 + 2*t];
                #pragma unroll
                for (int mt = 0; mt < 2; mt++) {
                    float e0 = ex2f(sc[mt][l][0] + mf.x);
                    float e1 = ex2f(sc[mt][l][1] + mf.y);
                    float e2 = ex2f(sc[mt][l][2] + mf.x);
                    float e3 = ex2f(sc[mt][l][3] + mf.y);
                    lsum[mt][0] += e0 + e1;
                    lsum[mt][1] += e2 + e3;
                    pfrag[mt][2*gnt    ] = pack_bf2(e0, e1);
                    pfrag[mt][2*gnt + 1] = pack_bf2(e2, e3);
                }
            }
        }

        #pragma unroll
        for (int ks = 0; ks < 4; ks++) {
            #pragma unroll
            for (int p = 0; p < 4; p++) {
                unsigned bb[4];
                ldsm4t(bb, vB + cb + ks * (16 * AST * 2) + p * 32);
                #pragma unroll
                for (int mt = 0; mt < 2; mt++) {
                    mma16(oac[mt][2*p    ], &pfrag[mt][4*ks], bb);
                    mma16(oac[mt][2*p + 1], &pfrag[mt][4*ks], bb + 2);
                }
            }
        }
        __syncthreads();
    }

    #pragma unroll
    for (int mt = 0; mt < 2; mt++)
        #pragma unroll
        for (int j = 0; j < 2; j++) {
            float v = lsum[mt][j];
            v += __shfl_xor_sync(0xffffffffu, v, 1);
            v += __shfl_xor_sync(0xffffffffu, v, 2);
            lsum[mt][j] = 1.f / v;
        }

    #pragma unroll
    for (int dt = 0; dt < 8; dt++) {
        float p0 = oac[0][dt][0]*lsum[0][0] + oac[0][dt][2]*lsum[0][1]
                 + oac[1][dt][0]*lsum[1][0] + oac[1][dt][2]*lsum[1][1];
        float p1 = oac[0][dt][1]*lsum[0][0] + oac[0][dt][3]*lsum[0][1]
                 + oac[1][dt][1]*lsum[1][0] + oac[1][dt][3]*lsum[1][1];
        p0 += __shfl_xor_sync(0xffffffffu, p0, 4);
        p0 += __shfl_xor_sync(0xffffffffu, p0, 8);
        p0 += __shfl_xor_sync(0xffffffffu, p0, 16);
        p1 += __shfl_xor_sync(0xffffffffu, p1, 4);
        p1 += __shfl_xor_sync(0xffffffffu, p1, 8);
        p1 += __shfl_xor_sync(0xffffffffu, p1, 16);
        if (lane < 4) {
            atomicAdd(&spool[dt*8 + 2*t    ], p0);
            atomicAdd(&spool[dt*8 + 2*t + 1], p1);
        }
    }
    __syncthreads();
    if (tid < 64) {
        const int h = bh & 15;
        atomicAdd(&g_pooled[b*E_ + h*64 + tid], spool[tid]);
    }
}

// =====================================================================
// head A: o = (pooled/S) @ Wo^T + bo ; accumulate squared norm
// =====================================================================
__global__ __launch_bounds__(256) void headA_kernel(
    const float* __restrict__ Wo, const float* __restrict__ bo)
{
    const int b = blockIdx.y;
    const int n = blockIdx.x * 8 + (threadIdx.x >> 5);
    const int lane = threadIdx.x & 31;
    const float* pr = g_pooled + b * E_;
    const float* wr = Wo + (size_t)n * E_;
    float acc = 0.f;
    #pragma unroll
    for (int i = 0; i < 8; i++) {
        int k = i * 128 + lane * 4;
        float4 w = *(const float4*)(wr + k);
        float4 p = *(const float4*)(pr + k);
        acc += p.x*w.x + p.y*w.y + p.z*w.z + p.w*w.w;
    }
    #pragma unroll
    for (int off = 16; off > 0; off >>= 1)
        acc += __shfl_xor_sync(0xffffffffu, acc, off);
    if (lane == 0) {
        float o = acc * (1.0f / S_) + bo[n];
        g_o[b * E_ + n] = o;
        atomicAdd(&g_nrm[b], o * o);
    }
}

// =====================================================================
// head B: u = o/||o|| - text ; h = relu(u @ W1^T + b1) ; score += h*W2
// =====================================================================
__global__ __launch_bounds__(256) void headB_kernel(
    const float* __restrict__ text,
    const float* __restrict__ W1, const float* __restrict__ b1,
    const float* __restrict__ W2)
{
    const int b = blockIdx.y;
    const int rr = blockIdx.x * 8 + (threadIdx.x >> 5);
    const int lane = threadIdx.x & 31;
    const float rinv = rsqrtf(g_nrm[b]);
    const float* orow = g_o + b * E_;
    const float* trow = text + b * E_;
    const float* wr = W1 + (size_t)rr * E_;
    float acc = 0.f;
    #pragma unroll
    for (int i = 0; i < 8; i++) {
        int k = i * 128 + lane * 4;
        float4 w = *(const float4*)(wr + k);
        float4 o = *(const float4*)(orow + k);
        float4 tt = *(const float4*)(trow + k);
        acc += (o.x*rinv - tt.x)*w.x + (o.y*rinv - tt.y)*w.y
             + (o.z*rinv - tt.z)*w.z + (o.w*rinv - tt.w)*w.w;
    }
    #pragma unroll
    for (int off = 16; off > 0; off >>= 1)
        acc += __shfl_xor_sync(0xffffffffu, acc, off);
    if (lane == 0) {
        float hv = fmaxf(acc + b1[rr], 0.f);
        atomicAdd(&g_score[b], hv * W2[rr]);
    }
}

__global__ void headC_kernel(const float* __restrict__ b2, float* __restrict__ out)
{
    int i = threadIdx.x;
    if (i < B_) out[i] = tanhf(g_score[i] + b2[0]);
}

// =====================================================================
// Launch
// =====================================================================
extern "C" void kernel_launch(void* const* d_in, const int* in_sizes, int n_in,
                              void* d_out, int out_size)
{
    (void)in_sizes; (void)n_in; (void)out_size;
    const float* x    = (const float*)d_in[0];
    const int*   mask = (const int*)  d_in[1];
    const float* text = (const float*)d_in[2];
    const float* Wq = (const float*)d_in[3];
    const float* bq = (const float*)d_in[4];
    const float* Wk = (const float*)d_in[5];
    const float* bk = (const float*)d_in[6];
    const float* Wv = (const float*)d_in[7];
    const float* bv = (const float*)d_in[8];
    const float* Wo = (const float*)d_in[9];
    const float* bo = (const float*)d_in[10];
    const float* W1 = (const float*)d_in[11];
    const float* b1 = (const float*)d_in[12];
    const float* W2 = (const float*)d_in[13];
    const float* b2 = (const float*)d_in[14];
    float* out = (float*)d_out;

    cudaFuncSetAttribute(attn_mma, cudaFuncAttributeMaxDynamicSharedMemorySize, ATTN_SMEM);
    cudaFuncSetAttribute(qkv_mma, cudaFuncAttributeMaxDynamicSharedMemorySize, QKV_SMEM);

    {
        int total = (XN + 3*WN) / 4;
        cvt_kernel<<<(total + 255) / 256, 256>>>(x, Wq, Wk, Wv);
    }
    qkv_mma<<<dim3(8, 64, 3), 256, QKV_SMEM>>>(bq, bk, bv);
    attn_mma<<<dim3(8, 64), 256, ATTN_SMEM>>>(mask);
    headA_kernel<<<dim3(128, B_), 256>>>(Wo, bo);
    headB_kernel<<<dim3(64, B_), 256>>>(text, W1, b1, W2);
    headC_kernel<<<1, 32>>>(b2, out);
}